// round 2
// baseline (speedup 1.0000x reference)
#include <cuda_runtime.h>
#include <math.h>

#define SEQ    3072
#define HID    1536
#define NH     12
#define HD     128
#define QKVW   4608   // 3*HID
#define INTER  13696
#define MAXL   1024   // max segment length for this problem instance
#define EPS    1e-6f

// ---------------- scratch (static device memory; no allocations allowed) ----
__device__ float g_hnorm [SEQ * HID];
__device__ float g_qkv   [SEQ * QKVW];
__device__ float g_scores[NH * SEQ * MAXL];
__device__ float g_attn  [SEQ * HID];
__device__ float g_hid2  [SEQ * HID];
__device__ float g_h2n   [SEQ * HID];
__device__ float g_gate  [SEQ * INTER];
__device__ float g_up    [SEQ * INTER];

// ---------------- RMSNorm: one block per row (1536 elems) -------------------
__global__ void rmsnorm_kernel(const float* __restrict__ x,
                               const float* __restrict__ w,
                               float* __restrict__ y) {
    int row = blockIdx.x;
    const float* xr = x + row * HID;
    float* yr = y + row * HID;
    int tid = threadIdx.x;

    float ss = 0.f;
    for (int i = tid; i < HID; i += 256) {
        float v = xr[i];
        ss += v * v;
    }
    __shared__ float red[256];
    red[tid] = ss;
    __syncthreads();
    for (int s = 128; s > 0; s >>= 1) {
        if (tid < s) red[tid] += red[tid + s];
        __syncthreads();
    }
    float inv = rsqrtf(red[0] / (float)HID + EPS);
    for (int i = tid; i < HID; i += 256) {
        yr[i] = xr[i] * inv * w[i];
    }
}

// ---------------- generic NN SGEMM: C = A@B (+ R), 128x128x16 tiles ---------
// A: [M,K] lda=K ; B: [K,N] ldb=N ; C,R: [M,N]. M%128==0, N%128==0, K%16==0.
__global__ __launch_bounds__(256) void sgemm_nn(const float* __restrict__ A,
                                                const float* __restrict__ B,
                                                const float* __restrict__ R,
                                                float* __restrict__ C,
                                                int M, int N, int K) {
    __shared__ float As[16][128];
    __shared__ float Bs[16][128];

    int tid = threadIdx.x;
    int tx = tid & 15;       // 0..15 -> col group
    int ty = tid >> 4;       // 0..15 -> row group
    const float* Ab = A + (size_t)blockIdx.y * 128 * K;
    const float* Bb = B + blockIdx.x * 128;

    float acc[8][8];
#pragma unroll
    for (int i = 0; i < 8; i++)
#pragma unroll
        for (int j = 0; j < 8; j++) acc[i][j] = 0.f;

    for (int k0 = 0; k0 < K; k0 += 16) {
#pragma unroll
        for (int i = 0; i < 2; i++) {
            int idx = tid + i * 256;
            int ar = idx >> 2;            // 0..127
            int ac = (idx & 3) * 4;       // 0,4,8,12
            float4 a = *(const float4*)(Ab + (size_t)ar * K + k0 + ac);
            As[ac + 0][ar] = a.x;
            As[ac + 1][ar] = a.y;
            As[ac + 2][ar] = a.z;
            As[ac + 3][ar] = a.w;
            int br = idx >> 5;            // 0..15
            int bc = idx & 31;            // 0..31
            float4 b = *(const float4*)(Bb + (size_t)(k0 + br) * N + bc * 4);
            *(float4*)&Bs[br][bc * 4] = b;
        }
        __syncthreads();
#pragma unroll
        for (int kk = 0; kk < 16; kk++) {
            float ra[8], rb[8];
#pragma unroll
            for (int i = 0; i < 8; i++) ra[i] = As[kk][ty * 8 + i];
#pragma unroll
            for (int j = 0; j < 8; j++) rb[j] = Bs[kk][tx * 8 + j];
#pragma unroll
            for (int i = 0; i < 8; i++)
#pragma unroll
                for (int j = 0; j < 8; j++) acc[i][j] = fmaf(ra[i], rb[j], acc[i][j]);
        }
        __syncthreads();
    }

    int row0 = blockIdx.y * 128 + ty * 8;
    int col0 = blockIdx.x * 128 + tx * 8;
#pragma unroll
    for (int i = 0; i < 8; i++) {
        size_t off = (size_t)(row0 + i) * N + col0;
        float4 v0 = make_float4(acc[i][0], acc[i][1], acc[i][2], acc[i][3]);
        float4 v1 = make_float4(acc[i][4], acc[i][5], acc[i][6], acc[i][7]);
        if (R) {
            float4 r0 = *(const float4*)(R + off);
            float4 r1 = *(const float4*)(R + off + 4);
            v0.x += r0.x; v0.y += r0.y; v0.z += r0.z; v0.w += r0.w;
            v1.x += r1.x; v1.y += r1.y; v1.z += r1.z; v1.w += r1.w;
        }
        *(float4*)(C + off) = v0;
        *(float4*)(C + off + 4) = v1;
    }
}

// ---------------- RoPE in-place on q,k inside g_qkv --------------------------
__global__ void rope_kernel(float* __restrict__ qkv, const float* __restrict__ rot) {
    int n = blockIdx.x;
    int h = blockIdx.y;
    int d = threadIdx.x;                  // 0..127
    float ang = rot[n * HD + d];
    float c = cosf(ang), s = sinf(ang);
    float* q = qkv + (size_t)n * QKVW + h * HD;
    float* k = q + HID;
    int p = (d < 64) ? d + 64 : d - 64;
    float sgn = (d < 64) ? -1.f : 1.f;
    float qv = q[d], kv = k[d];
    float qp = q[p], kp = k[p];
    __syncthreads();
    q[d] = qv * c + sgn * qp * s;
    k[d] = kv * c + sgn * kp * s;
}

// ---------------- scores: per (head, segment), S = Q @ K^T * scale ----------
__global__ __launch_bounds__(256) void attn_scores(const float* __restrict__ qkv,
                                                   const int* __restrict__ cu,
                                                   int nseg,
                                                   float* __restrict__ scores) {
    int h = blockIdx.z / nseg;
    int s = blockIdx.z % nseg;
    int s0 = cu[s], s1 = cu[s + 1];
    int L = s1 - s0;
    int q0 = blockIdx.y * 64;
    int kt0 = blockIdx.x * 64;
    if (q0 >= L || kt0 >= L) return;

    __shared__ float Qs[16][64];
    __shared__ float Ks[16][64];
    int tid = threadIdx.x;
    int tx = tid & 15, ty = tid >> 4;

    const float* Qb = qkv + (size_t)(s0 + q0) * QKVW + h * HD;
    const float* Kb = qkv + (size_t)(s0 + kt0) * QKVW + HID + h * HD;

    float acc[4][4];
#pragma unroll
    for (int i = 0; i < 4; i++)
#pragma unroll
        for (int j = 0; j < 4; j++) acc[i][j] = 0.f;

    for (int c0 = 0; c0 < HD; c0 += 16) {
#pragma unroll
        for (int i = 0; i < 4; i++) {
            int idx = tid + i * 256;
            int m = idx >> 4, k = idx & 15;
            Qs[k][m] = Qb[(size_t)m * QKVW + c0 + k];
            Ks[k][m] = Kb[(size_t)m * QKVW + c0 + k];
        }
        __syncthreads();
#pragma unroll
        for (int kk = 0; kk < 16; kk++) {
            float ra[4], rb[4];
#pragma unroll
            for (int i = 0; i < 4; i++) ra[i] = Qs[kk][ty * 4 + i];
#pragma unroll
            for (int j = 0; j < 4; j++) rb[j] = Ks[kk][tx * 4 + j];
#pragma unroll
            for (int i = 0; i < 4; i++)
#pragma unroll
                for (int j = 0; j < 4; j++) acc[i][j] = fmaf(ra[i], rb[j], acc[i][j]);
        }
        __syncthreads();
    }

    const float scale = 0.088388347648318447f; // 128^-0.5
#pragma unroll
    for (int i = 0; i < 4; i++) {
        int qg = s0 + q0 + ty * 4 + i;
#pragma unroll
        for (int j = 0; j < 4; j++) {
            scores[((size_t)h * SEQ + qg) * MAXL + kt0 + tx * 4 + j] = acc[i][j] * scale;
        }
    }
}

// ---------------- softmax over each (head, query) row within its segment ----
__global__ void softmax_rows(float* __restrict__ scores,
                             const int* __restrict__ cu, int nseg) {
    int row = blockIdx.x;            // 0 .. NH*SEQ-1
    int q = row % SEQ;
    int L = MAXL;
    for (int s = 0; s < nseg; s++) {
        if (q >= cu[s] && q < cu[s + 1]) { L = cu[s + 1] - cu[s]; break; }
    }
    float* r = scores + (size_t)row * MAXL;
    int tid = threadIdx.x;
    __shared__ float red[256];

    float m = -3.4e38f;
    for (int i = tid; i < L; i += 256) m = fmaxf(m, r[i]);
    red[tid] = m;
    __syncthreads();
    for (int s = 128; s > 0; s >>= 1) {
        if (tid < s) red[tid] = fmaxf(red[tid], red[tid + s]);
        __syncthreads();
    }
    m = red[0];
    __syncthreads();

    float sum = 0.f;
    for (int i = tid; i < L; i += 256) {
        float e = expf(r[i] - m);
        r[i] = e;
        sum += e;
    }
    red[tid] = sum;
    __syncthreads();
    for (int s = 128; s > 0; s >>= 1) {
        if (tid < s) red[tid] += red[tid + s];
        __syncthreads();
    }
    float inv = 1.f / red[0];
    for (int i = tid; i < L; i += 256) r[i] *= inv;
}

// ---------------- PV: per (head, segment), O = P @ V -------------------------
__global__ __launch_bounds__(256) void attn_pv(const float* __restrict__ scores,
                                               const float* __restrict__ qkv,
                                               const int* __restrict__ cu,
                                               int nseg,
                                               float* __restrict__ out) {
    int h = blockIdx.z / nseg;
    int s = blockIdx.z % nseg;
    int s0 = cu[s];
    int L = cu[s + 1] - s0;
    int q0 = blockIdx.y * 64;
    int n0 = blockIdx.x * 64;          // 0 or 64 (HD=128)
    if (q0 >= L) return;

    __shared__ float Ps[16][64];
    __shared__ float Vs[16][64];
    int tid = threadIdx.x;
    int tx = tid & 15, ty = tid >> 4;

    const float* Pb = scores + ((size_t)h * SEQ + s0 + q0) * MAXL;
    const float* Vb = qkv + (size_t)s0 * QKVW + 2 * HID + h * HD + n0;

    float acc[4][4];
#pragma unroll
    for (int i = 0; i < 4; i++)
#pragma unroll
        for (int j = 0; j < 4; j++) acc[i][j] = 0.f;

    for (int k0 = 0; k0 < L; k0 += 16) {
#pragma unroll
        for (int i = 0; i < 4; i++) {
            int idx = tid + i * 256;
            int m = idx >> 4, k = idx & 15;
            Ps[k][m] = Pb[(size_t)m * MAXL + k0 + k];
            int kv = idx >> 6, n = idx & 63;
            Vs[kv][n] = Vb[(size_t)(k0 + kv) * QKVW + n];
        }
        __syncthreads();
#pragma unroll
        for (int kk = 0; kk < 16; kk++) {
            float ra[4], rb[4];
#pragma unroll
            for (int i = 0; i < 4; i++) ra[i] = Ps[kk][ty * 4 + i];
#pragma unroll
            for (int j = 0; j < 4; j++) rb[j] = Vs[kk][tx * 4 + j];
#pragma unroll
            for (int i = 0; i < 4; i++)
#pragma unroll
                for (int j = 0; j < 4; j++) acc[i][j] = fmaf(ra[i], rb[j], acc[i][j]);
        }
        __syncthreads();
    }

#pragma unroll
    for (int i = 0; i < 4; i++) {
        int qg = s0 + q0 + ty * 4 + i;
#pragma unroll
        for (int j = 0; j < 4; j++) {
            out[(size_t)qg * HID + h * HD + n0 + tx * 4 + j] = acc[i][j];
        }
    }
}

// ---------------- SwiGLU activation: gate = silu(gate) * up -----------------
__global__ void silu_mul(float* __restrict__ gate, const float* __restrict__ up, int n) {
    int i = blockIdx.x * blockDim.x + threadIdx.x;
    if (i < n) {
        float g = gate[i];
        float sg = g / (1.f + expf(-g));
        gate[i] = sg * up[i];
    }
}

// ---------------- host orchestration ----------------------------------------
extern "C" void kernel_launch(void* const* d_in, const int* in_sizes, int n_in,
                              void* d_out, int out_size) {
    const float* hidden = (const float*)d_in[0];
    const float* rot    = (const float*)d_in[1];
    const float* n1w    = (const float*)d_in[2];
    const float* n2w    = (const float*)d_in[3];
    const float* qkv_w  = (const float*)d_in[4];
    const float* proj_w = (const float*)d_in[5];
    const float* gate_w = (const float*)d_in[6];
    const float* up_w   = (const float*)d_in[7];
    const float* down_w = (const float*)d_in[8];
    const int*   cu     = (const int*)d_in[9];
    float* out = (float*)d_out;

    int nseg = in_sizes[9] - 1;

    float *p_hnorm, *p_qkv, *p_scores, *p_attn, *p_hid2, *p_h2n, *p_gate, *p_up;
    cudaGetSymbolAddress((void**)&p_hnorm,  g_hnorm);
    cudaGetSymbolAddress((void**)&p_qkv,    g_qkv);
    cudaGetSymbolAddress((void**)&p_scores, g_scores);
    cudaGetSymbolAddress((void**)&p_attn,   g_attn);
    cudaGetSymbolAddress((void**)&p_hid2,   g_hid2);
    cudaGetSymbolAddress((void**)&p_h2n,    g_h2n);
    cudaGetSymbolAddress((void**)&p_gate,   g_gate);
    cudaGetSymbolAddress((void**)&p_up,     g_up);

    // 1. norm1
    rmsnorm_kernel<<<SEQ, 256>>>(hidden, n1w, p_hnorm);
    // 2. qkv = hnorm @ qkv_w
    sgemm_nn<<<dim3(QKVW / 128, SEQ / 128), 256>>>(p_hnorm, qkv_w, nullptr, p_qkv,
                                                   SEQ, QKVW, HID);
    // 3. rope on q,k (in place)
    rope_kernel<<<dim3(SEQ, NH), HD>>>(p_qkv, rot);
    // 4. scores per (head, segment)
    attn_scores<<<dim3(SEQ / 64, SEQ / 64, NH * nseg), 256>>>(p_qkv, cu, nseg, p_scores);
    // 5. softmax
    softmax_rows<<<NH * SEQ, 256>>>(p_scores, cu, nseg);
    // 6. O = P @ V
    attn_pv<<<dim3(HD / 64, SEQ / 64, NH * nseg), 256>>>(p_scores, p_qkv, cu, nseg, p_attn);
    // 7. hidden2 = attn @ proj_w + hidden
    sgemm_nn<<<dim3(HID / 128, SEQ / 128), 256>>>(p_attn, proj_w, hidden, p_hid2,
                                                  SEQ, HID, HID);
    // 8. norm2
    rmsnorm_kernel<<<SEQ, 256>>>(p_hid2, n2w, p_h2n);
    // 9/10. gate & up
    sgemm_nn<<<dim3(INTER / 128, SEQ / 128), 256>>>(p_h2n, gate_w, nullptr, p_gate,
                                                    SEQ, INTER, HID);
    sgemm_nn<<<dim3(INTER / 128, SEQ / 128), 256>>>(p_h2n, up_w, nullptr, p_up,
                                                    SEQ, INTER, HID);
    // 11. act = silu(gate) * up
    {
        int n = SEQ * INTER;
        silu_mul<<<(n + 255) / 256, 256>>>(p_gate, p_up, n);
    }
    // 12. out = act @ down_w + hidden2
    sgemm_nn<<<dim3(HID / 128, SEQ / 128), 256>>>(p_gate, down_w, p_hid2, out,
                                                  SEQ, HID, INTER);
}

// round 3
// speedup vs baseline: 1.0004x; 1.0004x over previous
#include <cuda_runtime.h>
#include <math.h>

#define SEQ    3072
#define HID    1536
#define NH     12
#define HD     128
#define QKVW   4608   // 3*HID
#define INTER  13696
#define MAXL   1024   // max segment length for this problem instance
#define EPS    1e-6f

// ---------------- scratch (static device memory; no allocations allowed) ----
__device__ float g_hnorm [SEQ * HID];
__device__ float g_qkv   [SEQ * QKVW];
__device__ float g_scores[NH * SEQ * MAXL];
__device__ float g_attn  [SEQ * HID];
__device__ float g_hid2  [SEQ * HID];
__device__ float g_h2n   [SEQ * HID];
__device__ float g_gate  [SEQ * INTER];
__device__ float g_up    [SEQ * INTER];

// ---------------- RMSNorm: one block per row (1536 elems) -------------------
__global__ void rmsnorm_kernel(const float* __restrict__ x,
                               const float* __restrict__ w,
                               float* __restrict__ y) {
    int row = blockIdx.x;
    const float* xr = x + row * HID;
    float* yr = y + row * HID;
    int tid = threadIdx.x;

    float ss = 0.f;
    for (int i = tid; i < HID; i += 256) {
        float v = xr[i];
        ss += v * v;
    }
    __shared__ float red[256];
    red[tid] = ss;
    __syncthreads();
    for (int s = 128; s > 0; s >>= 1) {
        if (tid < s) red[tid] += red[tid + s];
        __syncthreads();
    }
    float inv = rsqrtf(red[0] / (float)HID + EPS);
    for (int i = tid; i < HID; i += 256) {
        yr[i] = xr[i] * inv * w[i];
    }
}

// ---------------- generic NN SGEMM: C = A@B (+ R), 128x128x16 tiles ---------
// A: [M,K] lda=K ; B: [K,N] ldb=N ; C,R: [M,N]. M%128==0, N%128==0, K%16==0.
__global__ __launch_bounds__(256) void sgemm_nn(const float* __restrict__ A,
                                                const float* __restrict__ B,
                                                const float* __restrict__ R,
                                                float* __restrict__ C,
                                                int M, int N, int K) {
    __shared__ float As[16][128];
    __shared__ float Bs[16][128];

    int tid = threadIdx.x;
    int tx = tid & 15;       // 0..15 -> col group
    int ty = tid >> 4;       // 0..15 -> row group
    const float* Ab = A + (size_t)blockIdx.y * 128 * K;
    const float* Bb = B + blockIdx.x * 128;

    float acc[8][8];
#pragma unroll
    for (int i = 0; i < 8; i++)
#pragma unroll
        for (int j = 0; j < 8; j++) acc[i][j] = 0.f;

    for (int k0 = 0; k0 < K; k0 += 16) {
#pragma unroll
        for (int i = 0; i < 2; i++) {
            int idx = tid + i * 256;
            int ar = idx >> 2;            // 0..127
            int ac = (idx & 3) * 4;       // 0,4,8,12
            float4 a = *(const float4*)(Ab + (size_t)ar * K + k0 + ac);
            As[ac + 0][ar] = a.x;
            As[ac + 1][ar] = a.y;
            As[ac + 2][ar] = a.z;
            As[ac + 3][ar] = a.w;
            int br = idx >> 5;            // 0..15
            int bc = idx & 31;            // 0..31
            float4 b = *(const float4*)(Bb + (size_t)(k0 + br) * N + bc * 4);
            *(float4*)&Bs[br][bc * 4] = b;
        }
        __syncthreads();
#pragma unroll
        for (int kk = 0; kk < 16; kk++) {
            float ra[8], rb[8];
#pragma unroll
            for (int i = 0; i < 8; i++) ra[i] = As[kk][ty * 8 + i];
#pragma unroll
            for (int j = 0; j < 8; j++) rb[j] = Bs[kk][tx * 8 + j];
#pragma unroll
            for (int i = 0; i < 8; i++)
#pragma unroll
                for (int j = 0; j < 8; j++) acc[i][j] = fmaf(ra[i], rb[j], acc[i][j]);
        }
        __syncthreads();
    }

    int row0 = blockIdx.y * 128 + ty * 8;
    int col0 = blockIdx.x * 128 + tx * 8;
#pragma unroll
    for (int i = 0; i < 8; i++) {
        size_t off = (size_t)(row0 + i) * N + col0;
        float4 v0 = make_float4(acc[i][0], acc[i][1], acc[i][2], acc[i][3]);
        float4 v1 = make_float4(acc[i][4], acc[i][5], acc[i][6], acc[i][7]);
        if (R) {
            float4 r0 = *(const float4*)(R + off);
            float4 r1 = *(const float4*)(R + off + 4);
            v0.x += r0.x; v0.y += r0.y; v0.z += r0.z; v0.w += r0.w;
            v1.x += r1.x; v1.y += r1.y; v1.z += r1.z; v1.w += r1.w;
        }
        *(float4*)(C + off) = v0;
        *(float4*)(C + off + 4) = v1;
    }
}

// ---------------- RoPE in-place on q,k inside g_qkv --------------------------
__global__ void rope_kernel(float* __restrict__ qkv, const float* __restrict__ rot) {
    int n = blockIdx.x;
    int h = blockIdx.y;
    int d = threadIdx.x;                  // 0..127
    float ang = rot[n * HD + d];
    float c = cosf(ang), s = sinf(ang);
    float* q = qkv + (size_t)n * QKVW + h * HD;
    float* k = q + HID;
    int p = (d < 64) ? d + 64 : d - 64;
    float sgn = (d < 64) ? -1.f : 1.f;
    float qv = q[d], kv = k[d];
    float qp = q[p], kp = k[p];
    __syncthreads();
    q[d] = qv * c + sgn * qp * s;
    k[d] = kv * c + sgn * kp * s;
}

// ---------------- scores: per (head, segment), S = Q @ K^T * scale ----------
__global__ __launch_bounds__(256) void attn_scores(const float* __restrict__ qkv,
                                                   const int* __restrict__ cu,
                                                   int nseg,
                                                   float* __restrict__ scores) {
    int h = blockIdx.z / nseg;
    int s = blockIdx.z % nseg;
    int s0 = cu[s], s1 = cu[s + 1];
    int L = s1 - s0;
    int q0 = blockIdx.y * 64;
    int kt0 = blockIdx.x * 64;
    if (q0 >= L || kt0 >= L) return;

    __shared__ float Qs[16][64];
    __shared__ float Ks[16][64];
    int tid = threadIdx.x;
    int tx = tid & 15, ty = tid >> 4;

    const float* Qb = qkv + (size_t)(s0 + q0) * QKVW + h * HD;
    const float* Kb = qkv + (size_t)(s0 + kt0) * QKVW + HID + h * HD;

    float acc[4][4];
#pragma unroll
    for (int i = 0; i < 4; i++)
#pragma unroll
        for (int j = 0; j < 4; j++) acc[i][j] = 0.f;

    for (int c0 = 0; c0 < HD; c0 += 16) {
#pragma unroll
        for (int i = 0; i < 4; i++) {
            int idx = tid + i * 256;
            int m = idx >> 4, k = idx & 15;
            Qs[k][m] = Qb[(size_t)m * QKVW + c0 + k];
            Ks[k][m] = Kb[(size_t)m * QKVW + c0 + k];
        }
        __syncthreads();
#pragma unroll
        for (int kk = 0; kk < 16; kk++) {
            float ra[4], rb[4];
#pragma unroll
            for (int i = 0; i < 4; i++) ra[i] = Qs[kk][ty * 4 + i];
#pragma unroll
            for (int j = 0; j < 4; j++) rb[j] = Ks[kk][tx * 4 + j];
#pragma unroll
            for (int i = 0; i < 4; i++)
#pragma unroll
                for (int j = 0; j < 4; j++) acc[i][j] = fmaf(ra[i], rb[j], acc[i][j]);
        }
        __syncthreads();
    }

    const float scale = 0.088388347648318447f; // 128^-0.5
#pragma unroll
    for (int i = 0; i < 4; i++) {
        int qg = s0 + q0 + ty * 4 + i;
#pragma unroll
        for (int j = 0; j < 4; j++) {
            scores[((size_t)h * SEQ + qg) * MAXL + kt0 + tx * 4 + j] = acc[i][j] * scale;
        }
    }
}

// ---------------- softmax over each (head, query) row within its segment ----
__global__ void softmax_rows(float* __restrict__ scores,
                             const int* __restrict__ cu, int nseg) {
    int row = blockIdx.x;            // 0 .. NH*SEQ-1
    int q = row % SEQ;
    int L = MAXL;
    for (int s = 0; s < nseg; s++) {
        if (q >= cu[s] && q < cu[s + 1]) { L = cu[s + 1] - cu[s]; break; }
    }
    float* r = scores + (size_t)row * MAXL;
    int tid = threadIdx.x;
    __shared__ float red[256];

    float m = -3.4e38f;
    for (int i = tid; i < L; i += 256) m = fmaxf(m, r[i]);
    red[tid] = m;
    __syncthreads();
    for (int s = 128; s > 0; s >>= 1) {
        if (tid < s) red[tid] = fmaxf(red[tid], red[tid + s]);
        __syncthreads();
    }
    m = red[0];
    __syncthreads();

    float sum = 0.f;
    for (int i = tid; i < L; i += 256) {
        float e = expf(r[i] - m);
        r[i] = e;
        sum += e;
    }
    red[tid] = sum;
    __syncthreads();
    for (int s = 128; s > 0; s >>= 1) {
        if (tid < s) red[tid] += red[tid + s];
        __syncthreads();
    }
    float inv = 1.f / red[0];
    for (int i = tid; i < L; i += 256) r[i] *= inv;
}

// ---------------- PV: per (head, segment), O = P @ V -------------------------
__global__ __launch_bounds__(256) void attn_pv(const float* __restrict__ scores,
                                               const float* __restrict__ qkv,
                                               const int* __restrict__ cu,
                                               int nseg,
                                               float* __restrict__ out) {
    int h = blockIdx.z / nseg;
    int s = blockIdx.z % nseg;
    int s0 = cu[s];
    int L = cu[s + 1] - s0;
    int q0 = blockIdx.y * 64;
    int n0 = blockIdx.x * 64;          // 0 or 64 (HD=128)
    if (q0 >= L) return;

    __shared__ float Ps[16][64];
    __shared__ float Vs[16][64];
    int tid = threadIdx.x;
    int tx = tid & 15, ty = tid >> 4;

    const float* Pb = scores + ((size_t)h * SEQ + s0 + q0) * MAXL;
    const float* Vb = qkv + (size_t)s0 * QKVW + 2 * HID + h * HD + n0;

    float acc[4][4];
#pragma unroll
    for (int i = 0; i < 4; i++)
#pragma unroll
        for (int j = 0; j < 4; j++) acc[i][j] = 0.f;

    for (int k0 = 0; k0 < L; k0 += 16) {
#pragma unroll
        for (int i = 0; i < 4; i++) {
            int idx = tid + i * 256;
            int m = idx >> 4, k = idx & 15;
            Ps[k][m] = Pb[(size_t)m * MAXL + k0 + k];
            int kv = idx >> 6, n = idx & 63;
            Vs[kv][n] = Vb[(size_t)(k0 + kv) * QKVW + n];
        }
        __syncthreads();
#pragma unroll
        for (int kk = 0; kk < 16; kk++) {
            float ra[4], rb[4];
#pragma unroll
            for (int i = 0; i < 4; i++) ra[i] = Ps[kk][ty * 4 + i];
#pragma unroll
            for (int j = 0; j < 4; j++) rb[j] = Vs[kk][tx * 4 + j];
#pragma unroll
            for (int i = 0; i < 4; i++)
#pragma unroll
                for (int j = 0; j < 4; j++) acc[i][j] = fmaf(ra[i], rb[j], acc[i][j]);
        }
        __syncthreads();
    }

#pragma unroll
    for (int i = 0; i < 4; i++) {
        int qg = s0 + q0 + ty * 4 + i;
#pragma unroll
        for (int j = 0; j < 4; j++) {
            out[(size_t)qg * HID + h * HD + n0 + tx * 4 + j] = acc[i][j];
        }
    }
}

// ---------------- SwiGLU activation: gate = silu(gate) * up -----------------
__global__ void silu_mul(float* __restrict__ gate, const float* __restrict__ up, int n) {
    int i = blockIdx.x * blockDim.x + threadIdx.x;
    if (i < n) {
        float g = gate[i];
        float sg = g / (1.f + expf(-g));
        gate[i] = sg * up[i];
    }
}

// ---------------- host orchestration ----------------------------------------
extern "C" void kernel_launch(void* const* d_in, const int* in_sizes, int n_in,
                              void* d_out, int out_size) {
    const float* hidden = (const float*)d_in[0];
    const float* rot    = (const float*)d_in[1];
    const float* n1w    = (const float*)d_in[2];
    const float* n2w    = (const float*)d_in[3];
    const float* qkv_w  = (const float*)d_in[4];
    const float* proj_w = (const float*)d_in[5];
    const float* gate_w = (const float*)d_in[6];
    const float* up_w   = (const float*)d_in[7];
    const float* down_w = (const float*)d_in[8];
    const int*   cu     = (const int*)d_in[9];
    float* out = (float*)d_out;

    int nseg = in_sizes[9] - 1;

    float *p_hnorm, *p_qkv, *p_scores, *p_attn, *p_hid2, *p_h2n, *p_gate, *p_up;
    cudaGetSymbolAddress((void**)&p_hnorm,  g_hnorm);
    cudaGetSymbolAddress((void**)&p_qkv,    g_qkv);
    cudaGetSymbolAddress((void**)&p_scores, g_scores);
    cudaGetSymbolAddress((void**)&p_attn,   g_attn);
    cudaGetSymbolAddress((void**)&p_hid2,   g_hid2);
    cudaGetSymbolAddress((void**)&p_h2n,    g_h2n);
    cudaGetSymbolAddress((void**)&p_gate,   g_gate);
    cudaGetSymbolAddress((void**)&p_up,     g_up);

    // 1. norm1
    rmsnorm_kernel<<<SEQ, 256>>>(hidden, n1w, p_hnorm);
    // 2. qkv = hnorm @ qkv_w
    sgemm_nn<<<dim3(QKVW / 128, SEQ / 128), 256>>>(p_hnorm, qkv_w, nullptr, p_qkv,
                                                   SEQ, QKVW, HID);
    // 3. rope on q,k (in place)
    rope_kernel<<<dim3(SEQ, NH), HD>>>(p_qkv, rot);
    // 4. scores per (head, segment)
    attn_scores<<<dim3(SEQ / 64, SEQ / 64, NH * nseg), 256>>>(p_qkv, cu, nseg, p_scores);
    // 5. softmax
    softmax_rows<<<NH * SEQ, 256>>>(p_scores, cu, nseg);
    // 6. O = P @ V
    attn_pv<<<dim3(HD / 64, SEQ / 64, NH * nseg), 256>>>(p_scores, p_qkv, cu, nseg, p_attn);
    // 7. hidden2 = attn @ proj_w + hidden
    sgemm_nn<<<dim3(HID / 128, SEQ / 128), 256>>>(p_attn, proj_w, hidden, p_hid2,
                                                  SEQ, HID, HID);
    // 8. norm2
    rmsnorm_kernel<<<SEQ, 256>>>(p_hid2, n2w, p_h2n);
    // 9/10. gate & up
    sgemm_nn<<<dim3(INTER / 128, SEQ / 128), 256>>>(p_h2n, gate_w, nullptr, p_gate,
                                                    SEQ, INTER, HID);
    sgemm_nn<<<dim3(INTER / 128, SEQ / 128), 256>>>(p_h2n, up_w, nullptr, p_up,
                                                    SEQ, INTER, HID);
    // 11. act = silu(gate) * up
    {
        int n = SEQ * INTER;
        silu_mul<<<(n + 255) / 256, 256>>>(p_gate, p_up, n);
    }
    // 12. out = act @ down_w + hidden2
    sgemm_nn<<<dim3(HID / 128, SEQ / 128), 256>>>(p_gate, down_w, p_hid2, out,
                                                  SEQ, HID, INTER);
}

// round 5
// speedup vs baseline: 2.7381x; 2.7372x over previous
#include <cuda_runtime.h>
#include <cuda_bf16.h>
#include <cstdint>
#include <math.h>

#define SEQ    3072
#define HID    1536
#define NH     12
#define HD     128
#define QKVW   4608   // 3*HID
#define INTER  13696
#define MAXL   1024
#define EPS    1e-6f

// ===================== PTX helpers (baseline PTX only, no 'a' features) =====
__device__ __forceinline__ uint32_t smem_to_u32(const void* p) {
    uint32_t a;
    asm("{ .reg .u64 t; cvta.to.shared.u64 t, %1; cvt.u32.u64 %0, t; }"
        : "=r"(a) : "l"(p));
    return a;
}
__device__ __forceinline__ void cp_async16(uint32_t dst, const void* src) {
    asm volatile("cp.async.cg.shared.global [%0], [%1], 16;"
                 :: "r"(dst), "l"(src) : "memory");
}
#define CP_COMMIT() asm volatile("cp.async.commit_group;" ::: "memory")
#define CP_WAIT1()  asm volatile("cp.async.wait_group 1;" ::: "memory")
#define CP_WAIT0()  asm volatile("cp.async.wait_group 0;" ::: "memory")

__device__ __forceinline__ void ldsm4(uint32_t* r, uint32_t addr) {
    asm volatile("ldmatrix.sync.aligned.m8n8.x4.shared.b16 {%0,%1,%2,%3}, [%4];"
                 : "=r"(r[0]), "=r"(r[1]), "=r"(r[2]), "=r"(r[3]) : "r"(addr));
}
__device__ __forceinline__ void ldsm2(uint32_t* r, uint32_t addr) {
    asm volatile("ldmatrix.sync.aligned.m8n8.x2.shared.b16 {%0,%1}, [%2];"
                 : "=r"(r[0]), "=r"(r[1]) : "r"(addr));
}
__device__ __forceinline__ void mma_bf16(float* c, const uint32_t* a, const uint32_t* b) {
    asm volatile("mma.sync.aligned.m16n8k16.row.col.f32.bf16.bf16.f32 "
                 "{%0,%1,%2,%3}, {%4,%5,%6,%7}, {%8,%9}, {%0,%1,%2,%3};"
                 : "+f"(c[0]), "+f"(c[1]), "+f"(c[2]), "+f"(c[3])
                 : "r"(a[0]), "r"(a[1]), "r"(a[2]), "r"(a[3]),
                   "r"(b[0]), "r"(b[1]));
}
__device__ __forceinline__ void split_bf16(float v, __nv_bfloat16& h, __nv_bfloat16& l) {
    h = __float2bfloat16(v);
    l = __float2bfloat16(v - __bfloat162float(h));
}
__device__ __forceinline__ uint32_t sw128(uint32_t off) {
    return off ^ ((off >> 3) & 0x70);
}

// ===================== scratch =============================================
__device__ float g_qkv   [SEQ * QKVW];
__device__ float g_scores[(size_t)NH * SEQ * MAXL];
__device__ float g_hid2  [SEQ * HID];
__device__ float g_gate  [(size_t)SEQ * INTER];
__device__ float g_up    [(size_t)SEQ * INTER];

__device__ __nv_bfloat16 g_hn_h [SEQ * HID],  g_hn_l [SEQ * HID];
__device__ __nv_bfloat16 g_h2n_h[SEQ * HID],  g_h2n_l[SEQ * HID];
__device__ __nv_bfloat16 g_at_h [SEQ * HID],  g_at_l [SEQ * HID];
__device__ __nv_bfloat16 g_act_h[(size_t)SEQ * INTER], g_act_l[(size_t)SEQ * INTER];

// transposed bf16 weights: layout [N, K]
__device__ __nv_bfloat16 g_wqkv_h [(size_t)QKVW * HID],  g_wqkv_l [(size_t)QKVW * HID];
__device__ __nv_bfloat16 g_wproj_h[(size_t)HID * HID],   g_wproj_l[(size_t)HID * HID];
__device__ __nv_bfloat16 g_wgate_h[(size_t)INTER * HID], g_wgate_l[(size_t)INTER * HID];
__device__ __nv_bfloat16 g_wup_h  [(size_t)INTER * HID], g_wup_l  [(size_t)INTER * HID];
__device__ __nv_bfloat16 g_wdown_h[(size_t)HID * INTER], g_wdown_l[(size_t)HID * INTER];

// ===================== weight transpose + split =============================
// W: [K, N] fp32  ->  Th/Tl: [N, K] bf16
__global__ void wconv_t(const float* __restrict__ W, __nv_bfloat16* __restrict__ Th,
                        __nv_bfloat16* __restrict__ Tl, int K, int N) {
    __shared__ float ts[32][33];
    int n0 = blockIdx.x * 32, k0 = blockIdx.y * 32;
    int tx = threadIdx.x, ty = threadIdx.y;   // 32 x 8
#pragma unroll
    for (int r = 0; r < 32; r += 8)
        ts[ty + r][tx] = W[(size_t)(k0 + ty + r) * N + n0 + tx];
    __syncthreads();
#pragma unroll
    for (int r = 0; r < 32; r += 8) {
        float v = ts[tx][ty + r];             // W[k0+tx][n0+ty+r]
        __nv_bfloat16 h, l;
        split_bf16(v, h, l);
        size_t o = (size_t)(n0 + ty + r) * K + k0 + tx;
        Th[o] = h;
        Tl[o] = l;
    }
}

// ===================== mma.sync bf16x3 GEMM =================================
// C[M,N] = A[M,K] @ B[K,N] (+R). A: hi/lo bf16 [M,K]; B: hi/lo bf16 [N,K].
// grid (M/128, N/128), 256 threads. smem: 2 stages x 4 tiles x 16KB = 128KB.
__device__ __forceinline__ void load_chunk(
    uint32_t buf, int tid,
    const __nv_bfloat16* __restrict__ Ah, const __nv_bfloat16* __restrict__ Al,
    const __nv_bfloat16* __restrict__ Bh, const __nv_bfloat16* __restrict__ Bl,
    int m0, int n0, int k0, int K) {
#pragma unroll
    for (int t = 0; t < 16; t++) {
        int idx = tid + t * 256;
        int tile = idx >> 10;               // 0..3
        int w = idx & 1023;
        int r = w >> 3, c8 = w & 7;         // row 0..127, 16B group 0..7
        const __nv_bfloat16* src =
            (tile == 0 ? Ah : tile == 1 ? Al : tile == 2 ? Bh : Bl);
        int row = (tile < 2 ? m0 : n0) + r;
        uint32_t dst = buf + tile * 16384 + sw128((uint32_t)(r * 128 + c8 * 16));
        cp_async16(dst, src + (size_t)row * K + k0 + c8 * 8);
    }
}

__global__ __launch_bounds__(256, 1) void gemm_bf16x3(
    const __nv_bfloat16* __restrict__ Ah, const __nv_bfloat16* __restrict__ Al,
    const __nv_bfloat16* __restrict__ Bh, const __nv_bfloat16* __restrict__ Bl,
    const float* __restrict__ R, float* __restrict__ C, int N, int K) {
    extern __shared__ char smem[];
    const uint32_t sb = smem_to_u32(smem);
    const int tid = threadIdx.x;
    const int wid = tid >> 5;
    const int lane = tid & 31;
    const int wm = wid & 1;      // 0..1  (64-row slice)
    const int wn = wid >> 1;     // 0..3  (32-col slice)
    const int m0 = blockIdx.x * 128;
    const int n0 = blockIdx.y * 128;

    float acc[4][4][4];
#pragma unroll
    for (int i = 0; i < 4; i++)
#pragma unroll
        for (int j = 0; j < 4; j++)
#pragma unroll
            for (int k = 0; k < 4; k++) acc[i][j][k] = 0.f;

    const int nch = K >> 6;
    load_chunk(sb, tid, Ah, Al, Bh, Bl, m0, n0, 0, K);
    CP_COMMIT();

    for (int i = 0; i < nch; i++) {
        if (i + 1 < nch) {
            load_chunk(sb + ((i + 1) & 1) * 65536, tid, Ah, Al, Bh, Bl,
                       m0, n0, (i + 1) << 6, K);
            CP_COMMIT();
            CP_WAIT1();
        } else {
            CP_WAIT0();
        }
        __syncthreads();

        const uint32_t buf = sb + (i & 1) * 65536;
        const uint32_t bAh = buf;
        const uint32_t bAl = buf + 16384;
        const uint32_t bBh = buf + 32768;
        const uint32_t bBl = buf + 49152;

#pragma unroll
        for (int ks = 0; ks < 4; ks++) {
            // B fragments: 4 n-subtiles x {hi, lo}
            uint32_t bh[4][2], bl[4][2];
#pragma unroll
            for (int ni = 0; ni < 4; ni++) {
                uint32_t rowB = wn * 32 + ni * 8 + (lane & 7);
                uint32_t kb = ks * 32 + ((lane >> 3) & 1) * 16;
                uint32_t sw = sw128(rowB * 128 + kb);
                ldsm2(bh[ni], bBh + sw);
                ldsm2(bl[ni], bBl + sw);
            }
#pragma unroll
            for (int mi = 0; mi < 4; mi++) {
                uint32_t rowA = wm * 64 + mi * 16 + (lane & 15);
                uint32_t kb = ks * 32 + (lane >> 4) * 16;
                uint32_t sw = sw128(rowA * 128 + kb);
                uint32_t ah[4], al[4];
                ldsm4(ah, bAh + sw);
                ldsm4(al, bAl + sw);
#pragma unroll
                for (int ni = 0; ni < 4; ni++) {
                    mma_bf16(acc[mi][ni], ah, bh[ni]);
                    mma_bf16(acc[mi][ni], ah, bl[ni]);
                    mma_bf16(acc[mi][ni], al, bh[ni]);
                }
            }
        }
        __syncthreads();
    }

    // epilogue
    const int gr = lane >> 2;
    const int gc = (lane & 3) * 2;
#pragma unroll
    for (int mi = 0; mi < 4; mi++) {
        int r0 = m0 + wm * 64 + mi * 16 + gr;
#pragma unroll
        for (int ni = 0; ni < 4; ni++) {
            int c = n0 + wn * 32 + ni * 8 + gc;
            size_t o0 = (size_t)r0 * N + c;
            size_t o1 = (size_t)(r0 + 8) * N + c;
            float2 v0 = make_float2(acc[mi][ni][0], acc[mi][ni][1]);
            float2 v1 = make_float2(acc[mi][ni][2], acc[mi][ni][3]);
            if (R) {
                float2 rr0 = *(const float2*)(R + o0);
                float2 rr1 = *(const float2*)(R + o1);
                v0.x += rr0.x; v0.y += rr0.y;
                v1.x += rr1.x; v1.y += rr1.y;
            }
            *(float2*)(C + o0) = v0;
            *(float2*)(C + o1) = v1;
        }
    }
}

// ===================== RMSNorm -> bf16 hi/lo ================================
__global__ void rmsnorm_split(const float* __restrict__ x, const float* __restrict__ w,
                              __nv_bfloat16* __restrict__ yh, __nv_bfloat16* __restrict__ yl) {
    int row = blockIdx.x;
    const float* xr = x + (size_t)row * HID;
    int tid = threadIdx.x;
    float ss = 0.f;
    for (int i = tid; i < HID; i += 256) { float v = xr[i]; ss += v * v; }
    __shared__ float red[256];
    red[tid] = ss;
    __syncthreads();
    for (int s = 128; s > 0; s >>= 1) {
        if (tid < s) red[tid] += red[tid + s];
        __syncthreads();
    }
    float inv = rsqrtf(red[0] / (float)HID + EPS);
    for (int i = tid; i < HID; i += 256) {
        float v = xr[i] * inv * w[i];
        __nv_bfloat16 h, l;
        split_bf16(v, h, l);
        yh[(size_t)row * HID + i] = h;
        yl[(size_t)row * HID + i] = l;
    }
}

// ===================== RoPE (in-place fp32 on q,k) ==========================
__global__ void rope_kernel(float* __restrict__ qkv, const float* __restrict__ rot) {
    int n = blockIdx.x, h = blockIdx.y, d = threadIdx.x;
    float ang = rot[n * HD + d];
    float c = cosf(ang), s = sinf(ang);
    float* q = qkv + (size_t)n * QKVW + h * HD;
    float* k = q + HID;
    int p = (d < 64) ? d + 64 : d - 64;
    float sgn = (d < 64) ? -1.f : 1.f;
    float qv = q[d], kv = k[d], qp = q[p], kp = k[p];
    __syncthreads();
    q[d] = qv * c + sgn * qp * s;
    k[d] = kv * c + sgn * kp * s;
}

// ===================== attention (fp32 SIMT) ================================
__global__ __launch_bounds__(256) void attn_scores(const float* __restrict__ qkv,
                                                   const int* __restrict__ cu, int nseg,
                                                   float* __restrict__ scores) {
    int h = blockIdx.z / nseg, s = blockIdx.z % nseg;
    int s0 = cu[s], s1 = cu[s + 1];
    int L = s1 - s0;
    int q0 = blockIdx.y * 64, kt0 = blockIdx.x * 64;
    if (q0 >= L || kt0 >= L) return;
    __shared__ float Qs[16][64], Ks[16][64];
    int tid = threadIdx.x, tx = tid & 15, ty = tid >> 4;
    const float* Qb = qkv + (size_t)(s0 + q0) * QKVW + h * HD;
    const float* Kb = qkv + (size_t)(s0 + kt0) * QKVW + HID + h * HD;
    float acc[4][4];
#pragma unroll
    for (int i = 0; i < 4; i++)
#pragma unroll
        for (int j = 0; j < 4; j++) acc[i][j] = 0.f;
    for (int c0 = 0; c0 < HD; c0 += 16) {
#pragma unroll
        for (int i = 0; i < 4; i++) {
            int idx = tid + i * 256;
            int m = idx >> 4, k = idx & 15;
            Qs[k][m] = Qb[(size_t)m * QKVW + c0 + k];
            Ks[k][m] = Kb[(size_t)m * QKVW + c0 + k];
        }
        __syncthreads();
#pragma unroll
        for (int kk = 0; kk < 16; kk++) {
            float ra[4], rb[4];
#pragma unroll
            for (int i = 0; i < 4; i++) ra[i] = Qs[kk][ty * 4 + i];
#pragma unroll
            for (int j = 0; j < 4; j++) rb[j] = Ks[kk][tx * 4 + j];
#pragma unroll
            for (int i = 0; i < 4; i++)
#pragma unroll
                for (int j = 0; j < 4; j++) acc[i][j] = fmaf(ra[i], rb[j], acc[i][j]);
        }
        __syncthreads();
    }
    const float scale = 0.088388347648318447f;
#pragma unroll
    for (int i = 0; i < 4; i++) {
        int qg = s0 + q0 + ty * 4 + i;
#pragma unroll
        for (int j = 0; j < 4; j++)
            scores[((size_t)h * SEQ + qg) * MAXL + kt0 + tx * 4 + j] = acc[i][j] * scale;
    }
}

__global__ void softmax_rows(float* __restrict__ scores, const int* __restrict__ cu, int nseg) {
    int row = blockIdx.x;
    int q = row % SEQ;
    int L = MAXL;
    for (int s = 0; s < nseg; s++)
        if (q >= cu[s] && q < cu[s + 1]) { L = cu[s + 1] - cu[s]; break; }
    float* r = scores + (size_t)row * MAXL;
    int tid = threadIdx.x;
    __shared__ float red[256];
    float m = -3.4e38f;
    for (int i = tid; i < L; i += 256) m = fmaxf(m, r[i]);
    red[tid] = m;
    __syncthreads();
    for (int s = 128; s > 0; s >>= 1) {
        if (tid < s) red[tid] = fmaxf(red[tid], red[tid + s]);
        __syncthreads();
    }
    m = red[0];
    __syncthreads();
    float sum = 0.f;
    for (int i = tid; i < L; i += 256) {
        float e = expf(r[i] - m);
        r[i] = e;
        sum += e;
    }
    red[tid] = sum;
    __syncthreads();
    for (int s = 128; s > 0; s >>= 1) {
        if (tid < s) red[tid] += red[tid + s];
        __syncthreads();
    }
    float inv = 1.f / red[0];
    for (int i = tid; i < L; i += 256) r[i] *= inv;
}

__global__ __launch_bounds__(256) void attn_pv(const float* __restrict__ scores,
                                               const float* __restrict__ qkv,
                                               const int* __restrict__ cu, int nseg,
                                               __nv_bfloat16* __restrict__ oh,
                                               __nv_bfloat16* __restrict__ ol) {
    int h = blockIdx.z / nseg, s = blockIdx.z % nseg;
    int s0 = cu[s];
    int L = cu[s + 1] - s0;
    int q0 = blockIdx.y * 64, n0 = blockIdx.x * 64;
    if (q0 >= L) return;
    __shared__ float Ps[16][64], Vs[16][64];
    int tid = threadIdx.x, tx = tid & 15, ty = tid >> 4;
    const float* Pb = scores + ((size_t)h * SEQ + s0 + q0) * MAXL;
    const float* Vb = qkv + (size_t)s0 * QKVW + 2 * HID + h * HD + n0;
    float acc[4][4];
#pragma unroll
    for (int i = 0; i < 4; i++)
#pragma unroll
        for (int j = 0; j < 4; j++) acc[i][j] = 0.f;
    for (int k0 = 0; k0 < L; k0 += 16) {
#pragma unroll
        for (int i = 0; i < 4; i++) {
            int idx = tid + i * 256;
            int m = idx >> 4, k = idx & 15;
            Ps[k][m] = Pb[(size_t)m * MAXL + k0 + k];
            int kv = idx >> 6, n = idx & 63;
            Vs[kv][n] = Vb[(size_t)(k0 + kv) * QKVW + n];
        }
        __syncthreads();
#pragma unroll
        for (int kk = 0; kk < 16; kk++) {
            float ra[4], rb[4];
#pragma unroll
            for (int i = 0; i < 4; i++) ra[i] = Ps[kk][ty * 4 + i];
#pragma unroll
            for (int j = 0; j < 4; j++) rb[j] = Vs[kk][tx * 4 + j];
#pragma unroll
            for (int i = 0; i < 4; i++)
#pragma unroll
                for (int j = 0; j < 4; j++) acc[i][j] = fmaf(ra[i], rb[j], acc[i][j]);
        }
        __syncthreads();
    }
#pragma unroll
    for (int i = 0; i < 4; i++) {
        int qg = s0 + q0 + ty * 4 + i;
#pragma unroll
        for (int j = 0; j < 4; j++) {
            __nv_bfloat16 hh, ll;
            split_bf16(acc[i][j], hh, ll);
            size_t o = (size_t)qg * HID + h * HD + n0 + tx * 4 + j;
            oh[o] = hh;
            ol[o] = ll;
        }
    }
}

// ===================== SwiGLU -> bf16 hi/lo =================================
__global__ void silu_mul_split(const float* __restrict__ gate, const float* __restrict__ up,
                               __nv_bfloat16* __restrict__ ah, __nv_bfloat16* __restrict__ al,
                               size_t n) {
    size_t i = (size_t)blockIdx.x * blockDim.x + threadIdx.x;
    if (i < n) {
        float g = gate[i];
        float v = (g / (1.f + expf(-g))) * up[i];
        __nv_bfloat16 h, l;
        split_bf16(v, h, l);
        ah[i] = h;
        al[i] = l;
    }
}

// ===================== host orchestration ===================================
extern "C" void kernel_launch(void* const* d_in, const int* in_sizes, int n_in,
                              void* d_out, int out_size) {
    const float* hidden = (const float*)d_in[0];
    const float* rot    = (const float*)d_in[1];
    const float* n1w    = (const float*)d_in[2];
    const float* n2w    = (const float*)d_in[3];
    const float* qkv_w  = (const float*)d_in[4];
    const float* proj_w = (const float*)d_in[5];
    const float* gate_w = (const float*)d_in[6];
    const float* up_w   = (const float*)d_in[7];
    const float* down_w = (const float*)d_in[8];
    const int*   cu     = (const int*)d_in[9];
    float* out = (float*)d_out;
    int nseg = in_sizes[9] - 1;

    const int GEMM_SMEM = 2 * 65536;
    cudaFuncSetAttribute(gemm_bf16x3, cudaFuncAttributeMaxDynamicSharedMemorySize, GEMM_SMEM);

    float *p_qkv, *p_scores, *p_hid2, *p_gate, *p_up;
    cudaGetSymbolAddress((void**)&p_qkv,    g_qkv);
    cudaGetSymbolAddress((void**)&p_scores, g_scores);
    cudaGetSymbolAddress((void**)&p_hid2,   g_hid2);
    cudaGetSymbolAddress((void**)&p_gate,   g_gate);
    cudaGetSymbolAddress((void**)&p_up,     g_up);
    __nv_bfloat16 *hn_h, *hn_l, *h2n_h, *h2n_l, *at_h, *at_l, *act_h, *act_l;
    __nv_bfloat16 *wq_h, *wq_l, *wp_h, *wp_l, *wg_h, *wg_l, *wu_h, *wu_l, *wd_h, *wd_l;
    cudaGetSymbolAddress((void**)&hn_h, g_hn_h);   cudaGetSymbolAddress((void**)&hn_l, g_hn_l);
    cudaGetSymbolAddress((void**)&h2n_h, g_h2n_h); cudaGetSymbolAddress((void**)&h2n_l, g_h2n_l);
    cudaGetSymbolAddress((void**)&at_h, g_at_h);   cudaGetSymbolAddress((void**)&at_l, g_at_l);
    cudaGetSymbolAddress((void**)&act_h, g_act_h); cudaGetSymbolAddress((void**)&act_l, g_act_l);
    cudaGetSymbolAddress((void**)&wq_h, g_wqkv_h); cudaGetSymbolAddress((void**)&wq_l, g_wqkv_l);
    cudaGetSymbolAddress((void**)&wp_h, g_wproj_h);cudaGetSymbolAddress((void**)&wp_l, g_wproj_l);
    cudaGetSymbolAddress((void**)&wg_h, g_wgate_h);cudaGetSymbolAddress((void**)&wg_l, g_wgate_l);
    cudaGetSymbolAddress((void**)&wu_h, g_wup_h);  cudaGetSymbolAddress((void**)&wu_l, g_wup_l);
    cudaGetSymbolAddress((void**)&wd_h, g_wdown_h);cudaGetSymbolAddress((void**)&wd_l, g_wdown_l);

    dim3 tb(32, 8);
    // weight transpose+split: W[K,N] -> T[N,K] hi/lo bf16
    wconv_t<<<dim3(QKVW / 32, HID / 32), tb>>>(qkv_w, wq_h, wq_l, HID, QKVW);
    wconv_t<<<dim3(HID / 32, HID / 32), tb>>>(proj_w, wp_h, wp_l, HID, HID);
    wconv_t<<<dim3(INTER / 32, HID / 32), tb>>>(gate_w, wg_h, wg_l, HID, INTER);
    wconv_t<<<dim3(INTER / 32, HID / 32), tb>>>(up_w, wu_h, wu_l, HID, INTER);
    wconv_t<<<dim3(HID / 32, INTER / 32), tb>>>(down_w, wd_h, wd_l, INTER, HID);

    // 1. norm1 -> bf16 hi/lo
    rmsnorm_split<<<SEQ, 256>>>(hidden, n1w, hn_h, hn_l);
    // 2. qkv = hnorm @ qkv_w  (fp32 out)
    gemm_bf16x3<<<dim3(SEQ / 128, QKVW / 128), 256, GEMM_SMEM>>>(
        hn_h, hn_l, wq_h, wq_l, nullptr, p_qkv, QKVW, HID);
    // 3. rope
    rope_kernel<<<dim3(SEQ, NH), HD>>>(p_qkv, rot);
    // 4-6. attention
    attn_scores<<<dim3(SEQ / 64, SEQ / 64, NH * nseg), 256>>>(p_qkv, cu, nseg, p_scores);
    softmax_rows<<<NH * SEQ, 256>>>(p_scores, cu, nseg);
    attn_pv<<<dim3(HD / 64, SEQ / 64, NH * nseg), 256>>>(p_scores, p_qkv, cu, nseg, at_h, at_l);
    // 7. hid2 = attn @ proj_w + hidden
    gemm_bf16x3<<<dim3(SEQ / 128, HID / 128), 256, GEMM_SMEM>>>(
        at_h, at_l, wp_h, wp_l, hidden, p_hid2, HID, HID);
    // 8. norm2 -> bf16 hi/lo
    rmsnorm_split<<<SEQ, 256>>>(p_hid2, n2w, h2n_h, h2n_l);
    // 9/10. gate & up (fp32 out)
    gemm_bf16x3<<<dim3(SEQ / 128, INTER / 128), 256, GEMM_SMEM>>>(
        h2n_h, h2n_l, wg_h, wg_l, nullptr, p_gate, INTER, HID);
    gemm_bf16x3<<<dim3(SEQ / 128, INTER / 128), 256, GEMM_SMEM>>>(
        h2n_h, h2n_l, wu_h, wu_l, nullptr, p_up, INTER, HID);
    // 11. act = silu(gate)*up -> bf16 hi/lo
    {
        size_t n = (size_t)SEQ * INTER;
        silu_mul_split<<<(unsigned)((n + 255) / 256), 256>>>(p_gate, p_up, act_h, act_l, n);
    }
    // 12. out = act @ down_w + hid2
    gemm_bf16x3<<<dim3(SEQ / 128, HID / 128), 256, GEMM_SMEM>>>(
        act_h, act_l, wd_h, wd_l, p_hid2, out, HID, INTER);
}

// round 6
// speedup vs baseline: 2.7386x; 1.0002x over previous
#include <cuda_runtime.h>
#include <cuda_bf16.h>
#include <cstdint>
#include <math.h>

#define SEQ    3072
#define HID    1536
#define NH     12
#define HD     128
#define QKVW   4608   // 3*HID
#define INTER  13696
#define MAXL   1024
#define EPS    1e-6f

// ===================== PTX helpers (baseline PTX only, no 'a' features) =====
__device__ __forceinline__ uint32_t smem_to_u32(const void* p) {
    uint32_t a;
    asm("{ .reg .u64 t; cvta.to.shared.u64 t, %1; cvt.u32.u64 %0, t; }"
        : "=r"(a) : "l"(p));
    return a;
}
__device__ __forceinline__ void cp_async16(uint32_t dst, const void* src) {
    asm volatile("cp.async.cg.shared.global [%0], [%1], 16;"
                 :: "r"(dst), "l"(src) : "memory");
}
#define CP_COMMIT() asm volatile("cp.async.commit_group;" ::: "memory")
#define CP_WAIT1()  asm volatile("cp.async.wait_group 1;" ::: "memory")
#define CP_WAIT0()  asm volatile("cp.async.wait_group 0;" ::: "memory")

__device__ __forceinline__ void ldsm4(uint32_t* r, uint32_t addr) {
    asm volatile("ldmatrix.sync.aligned.m8n8.x4.shared.b16 {%0,%1,%2,%3}, [%4];"
                 : "=r"(r[0]), "=r"(r[1]), "=r"(r[2]), "=r"(r[3]) : "r"(addr));
}
__device__ __forceinline__ void ldsm2(uint32_t* r, uint32_t addr) {
    asm volatile("ldmatrix.sync.aligned.m8n8.x2.shared.b16 {%0,%1}, [%2];"
                 : "=r"(r[0]), "=r"(r[1]) : "r"(addr));
}
__device__ __forceinline__ void mma_bf16(float* c, const uint32_t* a, const uint32_t* b) {
    asm volatile("mma.sync.aligned.m16n8k16.row.col.f32.bf16.bf16.f32 "
                 "{%0,%1,%2,%3}, {%4,%5,%6,%7}, {%8,%9}, {%0,%1,%2,%3};"
                 : "+f"(c[0]), "+f"(c[1]), "+f"(c[2]), "+f"(c[3])
                 : "r"(a[0]), "r"(a[1]), "r"(a[2]), "r"(a[3]),
                   "r"(b[0]), "r"(b[1]));
}
__device__ __forceinline__ void split_bf16(float v, __nv_bfloat16& h, __nv_bfloat16& l) {
    h = __float2bfloat16(v);
    l = __float2bfloat16(v - __bfloat162float(h));
}
__device__ __forceinline__ uint32_t sw128(uint32_t off) {
    return off ^ ((off >> 3) & 0x70);
}

// ===================== scratch =============================================
__device__ float g_qkv   [SEQ * QKVW];
__device__ float g_scores[(size_t)NH * SEQ * MAXL];
__device__ float g_hid2  [SEQ * HID];
__device__ float g_gate  [(size_t)SEQ * INTER];
__device__ float g_up    [(size_t)SEQ * INTER];

__device__ __nv_bfloat16 g_hn_h [SEQ * HID],  g_hn_l [SEQ * HID];
__device__ __nv_bfloat16 g_h2n_h[SEQ * HID],  g_h2n_l[SEQ * HID];
__device__ __nv_bfloat16 g_at_h [SEQ * HID],  g_at_l [SEQ * HID];
__device__ __nv_bfloat16 g_act_h[(size_t)SEQ * INTER], g_act_l[(size_t)SEQ * INTER];

// transposed bf16 weights: layout [N, K]
__device__ __nv_bfloat16 g_wqkv_h [(size_t)QKVW * HID],  g_wqkv_l [(size_t)QKVW * HID];
__device__ __nv_bfloat16 g_wproj_h[(size_t)HID * HID],   g_wproj_l[(size_t)HID * HID];
__device__ __nv_bfloat16 g_wgate_h[(size_t)INTER * HID], g_wgate_l[(size_t)INTER * HID];
__device__ __nv_bfloat16 g_wup_h  [(size_t)INTER * HID], g_wup_l  [(size_t)INTER * HID];
__device__ __nv_bfloat16 g_wdown_h[(size_t)HID * INTER], g_wdown_l[(size_t)HID * INTER];

// ===================== weight transpose + split =============================
// W: [K, N] fp32  ->  Th/Tl: [N, K] bf16
__global__ void wconv_t(const float* __restrict__ W, __nv_bfloat16* __restrict__ Th,
                        __nv_bfloat16* __restrict__ Tl, int K, int N) {
    __shared__ float ts[32][33];
    int n0 = blockIdx.x * 32, k0 = blockIdx.y * 32;
    int tx = threadIdx.x, ty = threadIdx.y;   // 32 x 8
#pragma unroll
    for (int r = 0; r < 32; r += 8)
        ts[ty + r][tx] = W[(size_t)(k0 + ty + r) * N + n0 + tx];
    __syncthreads();
#pragma unroll
    for (int r = 0; r < 32; r += 8) {
        float v = ts[tx][ty + r];             // W[k0+tx][n0+ty+r]
        __nv_bfloat16 h, l;
        split_bf16(v, h, l);
        size_t o = (size_t)(n0 + ty + r) * K + k0 + tx;
        Th[o] = h;
        Tl[o] = l;
    }
}

// ===================== mma.sync bf16x3 GEMM =================================
// C[M,N] = A[M,K] @ B[K,N] (+R). A: hi/lo bf16 [M,K]; B: hi/lo bf16 [N,K].
// grid (M/128, N/128), 256 threads. smem: 2 stages x 4 tiles x 16KB = 128KB.
__device__ __forceinline__ void load_chunk(
    uint32_t buf, int tid,
    const __nv_bfloat16* __restrict__ Ah, const __nv_bfloat16* __restrict__ Al,
    const __nv_bfloat16* __restrict__ Bh, const __nv_bfloat16* __restrict__ Bl,
    int m0, int n0, int k0, int K) {
#pragma unroll
    for (int t = 0; t < 16; t++) {
        int idx = tid + t * 256;
        int tile = idx >> 10;               // 0..3
        int w = idx & 1023;
        int r = w >> 3, c8 = w & 7;         // row 0..127, 16B group 0..7
        const __nv_bfloat16* src =
            (tile == 0 ? Ah : tile == 1 ? Al : tile == 2 ? Bh : Bl);
        int row = (tile < 2 ? m0 : n0) + r;
        uint32_t dst = buf + tile * 16384 + sw128((uint32_t)(r * 128 + c8 * 16));
        cp_async16(dst, src + (size_t)row * K + k0 + c8 * 8);
    }
}

__global__ __launch_bounds__(256, 1) void gemm_bf16x3(
    const __nv_bfloat16* __restrict__ Ah, const __nv_bfloat16* __restrict__ Al,
    const __nv_bfloat16* __restrict__ Bh, const __nv_bfloat16* __restrict__ Bl,
    const float* __restrict__ R, float* __restrict__ C, int N, int K) {
    extern __shared__ char smem[];
    const uint32_t sb = smem_to_u32(smem);
    const int tid = threadIdx.x;
    const int wid = tid >> 5;
    const int lane = tid & 31;
    const int wm = wid & 1;      // 0..1  (64-row slice)
    const int wn = wid >> 1;     // 0..3  (32-col slice)
    const int m0 = blockIdx.x * 128;
    const int n0 = blockIdx.y * 128;

    float acc[4][4][4];
#pragma unroll
    for (int i = 0; i < 4; i++)
#pragma unroll
        for (int j = 0; j < 4; j++)
#pragma unroll
            for (int k = 0; k < 4; k++) acc[i][j][k] = 0.f;

    const int nch = K >> 6;
    load_chunk(sb, tid, Ah, Al, Bh, Bl, m0, n0, 0, K);
    CP_COMMIT();

    for (int i = 0; i < nch; i++) {
        if (i + 1 < nch) {
            load_chunk(sb + ((i + 1) & 1) * 65536, tid, Ah, Al, Bh, Bl,
                       m0, n0, (i + 1) << 6, K);
            CP_COMMIT();
            CP_WAIT1();
        } else {
            CP_WAIT0();
        }
        __syncthreads();

        const uint32_t buf = sb + (i & 1) * 65536;
        const uint32_t bAh = buf;
        const uint32_t bAl = buf + 16384;
        const uint32_t bBh = buf + 32768;
        const uint32_t bBl = buf + 49152;

#pragma unroll
        for (int ks = 0; ks < 4; ks++) {
            // B fragments: 4 n-subtiles x {hi, lo}
            uint32_t bh[4][2], bl[4][2];
#pragma unroll
            for (int ni = 0; ni < 4; ni++) {
                uint32_t rowB = wn * 32 + ni * 8 + (lane & 7);
                uint32_t kb = ks * 32 + ((lane >> 3) & 1) * 16;
                uint32_t sw = sw128(rowB * 128 + kb);
                ldsm2(bh[ni], bBh + sw);
                ldsm2(bl[ni], bBl + sw);
            }
#pragma unroll
            for (int mi = 0; mi < 4; mi++) {
                uint32_t rowA = wm * 64 + mi * 16 + (lane & 15);
                uint32_t kb = ks * 32 + (lane >> 4) * 16;
                uint32_t sw = sw128(rowA * 128 + kb);
                uint32_t ah[4], al[4];
                ldsm4(ah, bAh + sw);
                ldsm4(al, bAl + sw);
#pragma unroll
                for (int ni = 0; ni < 4; ni++) {
                    mma_bf16(acc[mi][ni], ah, bh[ni]);
                    mma_bf16(acc[mi][ni], ah, bl[ni]);
                    mma_bf16(acc[mi][ni], al, bh[ni]);
                }
            }
        }
        __syncthreads();
    }

    // epilogue
    const int gr = lane >> 2;
    const int gc = (lane & 3) * 2;
#pragma unroll
    for (int mi = 0; mi < 4; mi++) {
        int r0 = m0 + wm * 64 + mi * 16 + gr;
#pragma unroll
        for (int ni = 0; ni < 4; ni++) {
            int c = n0 + wn * 32 + ni * 8 + gc;
            size_t o0 = (size_t)r0 * N + c;
            size_t o1 = (size_t)(r0 + 8) * N + c;
            float2 v0 = make_float2(acc[mi][ni][0], acc[mi][ni][1]);
            float2 v1 = make_float2(acc[mi][ni][2], acc[mi][ni][3]);
            if (R) {
                float2 rr0 = *(const float2*)(R + o0);
                float2 rr1 = *(const float2*)(R + o1);
                v0.x += rr0.x; v0.y += rr0.y;
                v1.x += rr1.x; v1.y += rr1.y;
            }
            *(float2*)(C + o0) = v0;
            *(float2*)(C + o1) = v1;
        }
    }
}

// ===================== RMSNorm -> bf16 hi/lo ================================
__global__ void rmsnorm_split(const float* __restrict__ x, const float* __restrict__ w,
                              __nv_bfloat16* __restrict__ yh, __nv_bfloat16* __restrict__ yl) {
    int row = blockIdx.x;
    const float* xr = x + (size_t)row * HID;
    int tid = threadIdx.x;
    float ss = 0.f;
    for (int i = tid; i < HID; i += 256) { float v = xr[i]; ss += v * v; }
    __shared__ float red[256];
    red[tid] = ss;
    __syncthreads();
    for (int s = 128; s > 0; s >>= 1) {
        if (tid < s) red[tid] += red[tid + s];
        __syncthreads();
    }
    float inv = rsqrtf(red[0] / (float)HID + EPS);
    for (int i = tid; i < HID; i += 256) {
        float v = xr[i] * inv * w[i];
        __nv_bfloat16 h, l;
        split_bf16(v, h, l);
        yh[(size_t)row * HID + i] = h;
        yl[(size_t)row * HID + i] = l;
    }
}

// ===================== RoPE (in-place fp32 on q,k) ==========================
__global__ void rope_kernel(float* __restrict__ qkv, const float* __restrict__ rot) {
    int n = blockIdx.x, h = blockIdx.y, d = threadIdx.x;
    float ang = rot[n * HD + d];
    float c = cosf(ang), s = sinf(ang);
    float* q = qkv + (size_t)n * QKVW + h * HD;
    float* k = q + HID;
    int p = (d < 64) ? d + 64 : d - 64;
    float sgn = (d < 64) ? -1.f : 1.f;
    float qv = q[d], kv = k[d], qp = q[p], kp = k[p];
    __syncthreads();
    q[d] = qv * c + sgn * qp * s;
    k[d] = kv * c + sgn * kp * s;
}

// ===================== attention (fp32 SIMT) ================================
__global__ __launch_bounds__(256) void attn_scores(const float* __restrict__ qkv,
                                                   const int* __restrict__ cu, int nseg,
                                                   float* __restrict__ scores) {
    int h = blockIdx.z / nseg, s = blockIdx.z % nseg;
    int s0 = cu[s], s1 = cu[s + 1];
    int L = s1 - s0;
    int q0 = blockIdx.y * 64, kt0 = blockIdx.x * 64;
    if (q0 >= L || kt0 >= L) return;
    __shared__ float Qs[16][64], Ks[16][64];
    int tid = threadIdx.x, tx = tid & 15, ty = tid >> 4;
    const float* Qb = qkv + (size_t)(s0 + q0) * QKVW + h * HD;
    const float* Kb = qkv + (size_t)(s0 + kt0) * QKVW + HID + h * HD;
    float acc[4][4];
#pragma unroll
    for (int i = 0; i < 4; i++)
#pragma unroll
        for (int j = 0; j < 4; j++) acc[i][j] = 0.f;
    for (int c0 = 0; c0 < HD; c0 += 16) {
#pragma unroll
        for (int i = 0; i < 4; i++) {
            int idx = tid + i * 256;
            int m = idx >> 4, k = idx & 15;
            Qs[k][m] = Qb[(size_t)m * QKVW + c0 + k];
            Ks[k][m] = Kb[(size_t)m * QKVW + c0 + k];
        }
        __syncthreads();
#pragma unroll
        for (int kk = 0; kk < 16; kk++) {
            float ra[4], rb[4];
#pragma unroll
            for (int i = 0; i < 4; i++) ra[i] = Qs[kk][ty * 4 + i];
#pragma unroll
            for (int j = 0; j < 4; j++) rb[j] = Ks[kk][tx * 4 + j];
#pragma unroll
            for (int i = 0; i < 4; i++)
#pragma unroll
                for (int j = 0; j < 4; j++) acc[i][j] = fmaf(ra[i], rb[j], acc[i][j]);
        }
        __syncthreads();
    }
    const float scale = 0.088388347648318447f;
#pragma unroll
    for (int i = 0; i < 4; i++) {
        int qg = s0 + q0 + ty * 4 + i;
#pragma unroll
        for (int j = 0; j < 4; j++)
            scores[((size_t)h * SEQ + qg) * MAXL + kt0 + tx * 4 + j] = acc[i][j] * scale;
    }
}

__global__ void softmax_rows(float* __restrict__ scores, const int* __restrict__ cu, int nseg) {
    int row = blockIdx.x;
    int q = row % SEQ;
    int L = MAXL;
    for (int s = 0; s < nseg; s++)
        if (q >= cu[s] && q < cu[s + 1]) { L = cu[s + 1] - cu[s]; break; }
    float* r = scores + (size_t)row * MAXL;
    int tid = threadIdx.x;
    __shared__ float red[256];
    float m = -3.4e38f;
    for (int i = tid; i < L; i += 256) m = fmaxf(m, r[i]);
    red[tid] = m;
    __syncthreads();
    for (int s = 128; s > 0; s >>= 1) {
        if (tid < s) red[tid] = fmaxf(red[tid], red[tid + s]);
        __syncthreads();
    }
    m = red[0];
    __syncthreads();
    float sum = 0.f;
    for (int i = tid; i < L; i += 256) {
        float e = expf(r[i] - m);
        r[i] = e;
        sum += e;
    }
    red[tid] = sum;
    __syncthreads();
    for (int s = 128; s > 0; s >>= 1) {
        if (tid < s) red[tid] += red[tid + s];
        __syncthreads();
    }
    float inv = 1.f / red[0];
    for (int i = tid; i < L; i += 256) r[i] *= inv;
}

__global__ __launch_bounds__(256) void attn_pv(const float* __restrict__ scores,
                                               const float* __restrict__ qkv,
                                               const int* __restrict__ cu, int nseg,
                                               __nv_bfloat16* __restrict__ oh,
                                               __nv_bfloat16* __restrict__ ol) {
    int h = blockIdx.z / nseg, s = blockIdx.z % nseg;
    int s0 = cu[s];
    int L = cu[s + 1] - s0;
    int q0 = blockIdx.y * 64, n0 = blockIdx.x * 64;
    if (q0 >= L) return;
    __shared__ float Ps[16][64], Vs[16][64];
    int tid = threadIdx.x, tx = tid & 15, ty = tid >> 4;
    const float* Pb = scores + ((size_t)h * SEQ + s0 + q0) * MAXL;
    const float* Vb = qkv + (size_t)s0 * QKVW + 2 * HID + h * HD + n0;
    float acc[4][4];
#pragma unroll
    for (int i = 0; i < 4; i++)
#pragma unroll
        for (int j = 0; j < 4; j++) acc[i][j] = 0.f;
    for (int k0 = 0; k0 < L; k0 += 16) {
#pragma unroll
        for (int i = 0; i < 4; i++) {
            int idx = tid + i * 256;
            int m = idx >> 4, k = idx & 15;
            Ps[k][m] = Pb[(size_t)m * MAXL + k0 + k];
            int kv = idx >> 6, n = idx & 63;
            Vs[kv][n] = Vb[(size_t)(k0 + kv) * QKVW + n];
        }
        __syncthreads();
#pragma unroll
        for (int kk = 0; kk < 16; kk++) {
            float ra[4], rb[4];
#pragma unroll
            for (int i = 0; i < 4; i++) ra[i] = Ps[kk][ty * 4 + i];
#pragma unroll
            for (int j = 0; j < 4; j++) rb[j] = Vs[kk][tx * 4 + j];
#pragma unroll
            for (int i = 0; i < 4; i++)
#pragma unroll
                for (int j = 0; j < 4; j++) acc[i][j] = fmaf(ra[i], rb[j], acc[i][j]);
        }
        __syncthreads();
    }
#pragma unroll
    for (int i = 0; i < 4; i++) {
        int qg = s0 + q0 + ty * 4 + i;
#pragma unroll
        for (int j = 0; j < 4; j++) {
            __nv_bfloat16 hh, ll;
            split_bf16(acc[i][j], hh, ll);
            size_t o = (size_t)qg * HID + h * HD + n0 + tx * 4 + j;
            oh[o] = hh;
            ol[o] = ll;
        }
    }
}

// ===================== SwiGLU -> bf16 hi/lo =================================
__global__ void silu_mul_split(const float* __restrict__ gate, const float* __restrict__ up,
                               __nv_bfloat16* __restrict__ ah, __nv_bfloat16* __restrict__ al,
                               size_t n) {
    size_t i = (size_t)blockIdx.x * blockDim.x + threadIdx.x;
    if (i < n) {
        float g = gate[i];
        float v = (g / (1.f + expf(-g))) * up[i];
        __nv_bfloat16 h, l;
        split_bf16(v, h, l);
        ah[i] = h;
        al[i] = l;
    }
}

// ===================== host orchestration ===================================
extern "C" void kernel_launch(void* const* d_in, const int* in_sizes, int n_in,
                              void* d_out, int out_size) {
    const float* hidden = (const float*)d_in[0];
    const float* rot    = (const float*)d_in[1];
    const float* n1w    = (const float*)d_in[2];
    const float* n2w    = (const float*)d_in[3];
    const float* qkv_w  = (const float*)d_in[4];
    const float* proj_w = (const float*)d_in[5];
    const float* gate_w = (const float*)d_in[6];
    const float* up_w   = (const float*)d_in[7];
    const float* down_w = (const float*)d_in[8];
    const int*   cu     = (const int*)d_in[9];
    float* out = (float*)d_out;
    int nseg = in_sizes[9] - 1;

    const int GEMM_SMEM = 2 * 65536;
    cudaFuncSetAttribute(gemm_bf16x3, cudaFuncAttributeMaxDynamicSharedMemorySize, GEMM_SMEM);

    float *p_qkv, *p_scores, *p_hid2, *p_gate, *p_up;
    cudaGetSymbolAddress((void**)&p_qkv,    g_qkv);
    cudaGetSymbolAddress((void**)&p_scores, g_scores);
    cudaGetSymbolAddress((void**)&p_hid2,   g_hid2);
    cudaGetSymbolAddress((void**)&p_gate,   g_gate);
    cudaGetSymbolAddress((void**)&p_up,     g_up);
    __nv_bfloat16 *hn_h, *hn_l, *h2n_h, *h2n_l, *at_h, *at_l, *act_h, *act_l;
    __nv_bfloat16 *wq_h, *wq_l, *wp_h, *wp_l, *wg_h, *wg_l, *wu_h, *wu_l, *wd_h, *wd_l;
    cudaGetSymbolAddress((void**)&hn_h, g_hn_h);   cudaGetSymbolAddress((void**)&hn_l, g_hn_l);
    cudaGetSymbolAddress((void**)&h2n_h, g_h2n_h); cudaGetSymbolAddress((void**)&h2n_l, g_h2n_l);
    cudaGetSymbolAddress((void**)&at_h, g_at_h);   cudaGetSymbolAddress((void**)&at_l, g_at_l);
    cudaGetSymbolAddress((void**)&act_h, g_act_h); cudaGetSymbolAddress((void**)&act_l, g_act_l);
    cudaGetSymbolAddress((void**)&wq_h, g_wqkv_h); cudaGetSymbolAddress((void**)&wq_l, g_wqkv_l);
    cudaGetSymbolAddress((void**)&wp_h, g_wproj_h);cudaGetSymbolAddress((void**)&wp_l, g_wproj_l);
    cudaGetSymbolAddress((void**)&wg_h, g_wgate_h);cudaGetSymbolAddress((void**)&wg_l, g_wgate_l);
    cudaGetSymbolAddress((void**)&wu_h, g_wup_h);  cudaGetSymbolAddress((void**)&wu_l, g_wup_l);
    cudaGetSymbolAddress((void**)&wd_h, g_wdown_h);cudaGetSymbolAddress((void**)&wd_l, g_wdown_l);

    dim3 tb(32, 8);
    // weight transpose+split: W[K,N] -> T[N,K] hi/lo bf16
    wconv_t<<<dim3(QKVW / 32, HID / 32), tb>>>(qkv_w, wq_h, wq_l, HID, QKVW);
    wconv_t<<<dim3(HID / 32, HID / 32), tb>>>(proj_w, wp_h, wp_l, HID, HID);
    wconv_t<<<dim3(INTER / 32, HID / 32), tb>>>(gate_w, wg_h, wg_l, HID, INTER);
    wconv_t<<<dim3(INTER / 32, HID / 32), tb>>>(up_w, wu_h, wu_l, HID, INTER);
    wconv_t<<<dim3(HID / 32, INTER / 32), tb>>>(down_w, wd_h, wd_l, INTER, HID);

    // 1. norm1 -> bf16 hi/lo
    rmsnorm_split<<<SEQ, 256>>>(hidden, n1w, hn_h, hn_l);
    // 2. qkv = hnorm @ qkv_w  (fp32 out)
    gemm_bf16x3<<<dim3(SEQ / 128, QKVW / 128), 256, GEMM_SMEM>>>(
        hn_h, hn_l, wq_h, wq_l, nullptr, p_qkv, QKVW, HID);
    // 3. rope
    rope_kernel<<<dim3(SEQ, NH), HD>>>(p_qkv, rot);
    // 4-6. attention
    attn_scores<<<dim3(SEQ / 64, SEQ / 64, NH * nseg), 256>>>(p_qkv, cu, nseg, p_scores);
    softmax_rows<<<NH * SEQ, 256>>>(p_scores, cu, nseg);
    attn_pv<<<dim3(HD / 64, SEQ / 64, NH * nseg), 256>>>(p_scores, p_qkv, cu, nseg, at_h, at_l);
    // 7. hid2 = attn @ proj_w + hidden
    gemm_bf16x3<<<dim3(SEQ / 128, HID / 128), 256, GEMM_SMEM>>>(
        at_h, at_l, wp_h, wp_l, hidden, p_hid2, HID, HID);
    // 8. norm2 -> bf16 hi/lo
    rmsnorm_split<<<SEQ, 256>>>(p_hid2, n2w, h2n_h, h2n_l);
    // 9/10. gate & up (fp32 out)
    gemm_bf16x3<<<dim3(SEQ / 128, INTER / 128), 256, GEMM_SMEM>>>(
        h2n_h, h2n_l, wg_h, wg_l, nullptr, p_gate, INTER, HID);
    gemm_bf16x3<<<dim3(SEQ / 128, INTER / 128), 256, GEMM_SMEM>>>(
        h2n_h, h2n_l, wu_h, wu_l, nullptr, p_up, INTER, HID);
    // 11. act = silu(gate)*up -> bf16 hi/lo
    {
        size_t n = (size_t)SEQ * INTER;
        silu_mul_split<<<(unsigned)((n + 255) / 256), 256>>>(p_gate, p_up, act_h, act_l, n);
    }
    // 12. out = act @ down_w + hid2
    gemm_bf16x3<<<dim3(SEQ / 128, HID / 128), 256, GEMM_SMEM>>>(
        act_h, act_l, wd_h, wd_l, p_hid2, out, HID, INTER);
}